// round 3
// baseline (speedup 1.0000x reference)
#include <cuda_runtime.h>

#define N_NODES 100000
#define N_EDGES 1250000
#define IN_DIM  64
#define HID     128
#define OUT_DIM 64

// ---------------- scratch (static device globals; 16B-aligned via float4) --
__device__ float4 g_agg4[(size_t)N_NODES * IN_DIM / 4];   // 25.6 MB
__device__ float  g_deg [N_NODES];
__device__ float4 g_h1_4[(size_t)N_NODES * HID / 4];      // 51.2 MB
__device__ float4 g_h2_4[(size_t)N_NODES * HID / 4];      // 51.2 MB

// ---------------- helpers -------------------------------------------------
__device__ __forceinline__ void red_add_v4(float* p, float4 v) {
    asm volatile("red.global.add.v4.f32 [%0], {%1, %2, %3, %4};"
                 :: "l"(p), "f"(v.x), "f"(v.y), "f"(v.z), "f"(v.w)
                 : "memory");
}

// ---------------- zero agg + deg ------------------------------------------
__global__ void zero_kernel() {
    int i = blockIdx.x * blockDim.x + threadIdx.x;
    const int n4 = (N_NODES * IN_DIM) / 4;   // 1.6M float4
    if (i < n4) g_agg4[i] = make_float4(0.f, 0.f, 0.f, 0.f);
    if (i < N_NODES) g_deg[i] = 0.f;
}

// ---------------- scatter: agg[row] += x[col]; deg[row] += 1 --------------
// 8 threads per edge, each does 2x red.v4 (32 bytes).
// edge_index is INT32 on the wire (JAX x64 disabled).
__global__ void scatter_kernel(const float* __restrict__ x,
                               const int* __restrict__ ei) {
    long long t = (long long)blockIdx.x * blockDim.x + threadIdx.x;
    int e = (int)(t >> 3);
    if (e >= N_EDGES) return;
    int p = (int)(t & 7);
    int row = ei[e];
    int col = ei[N_EDGES + e];
    const float4* src = reinterpret_cast<const float4*>(x + (size_t)col * IN_DIM) + p * 2;
    float* dst = reinterpret_cast<float*>(g_agg4) + (size_t)row * IN_DIM + p * 8;
    float4 v0 = src[0];
    float4 v1 = src[1];
    red_add_v4(dst, v0);
    red_add_v4(dst + 4, v1);
    if (p == 0) atomicAdd(&g_deg[row], 1.0f);
}

// ---------------- finalize: agg /= max(deg,1) ------------------------------
__global__ void finalize_kernel() {
    int i = blockIdx.x * blockDim.x + threadIdx.x;   // over N_NODES*16 float4
    const int n4 = N_NODES * (IN_DIM / 4);
    if (i >= n4) return;
    int node = i / (IN_DIM / 4);
    float d = g_deg[node];
    float inv = 1.0f / fmaxf(d, 1.0f);
    float4 v = g_agg4[i];
    v.x *= inv; v.y *= inv; v.z *= inv; v.w *= inv;
    g_agg4[i] = v;
}

// ---------------- fused-layer SGEMM ---------------------------------------
// out[M, NOUT] = act(A[M,128] @ W[128,NOUT] + b)
// BM=64 rows per block, 256 threads, TM=8 x TN=NOUT/32 per thread.
template<int NOUT, bool RELU, bool CONCAT>
__global__ void mlp_kernel(const float* __restrict__ A,
                           const float* __restrict__ A2,
                           const float* __restrict__ W,
                           const float* __restrict__ bias,
                           float* __restrict__ out) {
    constexpr int K = 128;
    constexpr int BM = 64;
    constexpr int TN = NOUT / 32;
    constexpr int AS_STRIDE = 132;     // padded

    extern __shared__ float smem[];
    float* As = smem;                         // [BM][AS_STRIDE]
    float* Bs = smem + BM * AS_STRIDE;        // [K][NOUT]

    int tid = threadIdx.x;
    int m0 = blockIdx.x * BM;

    // --- fill As (BM x K), zero-padded past M ---
    for (int i = tid; i < BM * (K / 4); i += 256) {
        int m  = i >> 5;          // K/4 == 32
        int kq = i & 31;
        int node = m0 + m;
        float4 v = make_float4(0.f, 0.f, 0.f, 0.f);
        if (node < N_NODES) {
            if (CONCAT) {
                if (kq < 16) v = reinterpret_cast<const float4*>(A )[(size_t)node * 16 + kq];
                else         v = reinterpret_cast<const float4*>(A2)[(size_t)node * 16 + kq - 16];
            } else {
                v = reinterpret_cast<const float4*>(A)[(size_t)node * 32 + kq];
            }
        }
        float* d = As + m * AS_STRIDE + kq * 4;
        d[0] = v.x; d[1] = v.y; d[2] = v.z; d[3] = v.w;
    }
    // --- fill Bs (K x NOUT) ---
    for (int i = tid; i < K * NOUT / 4; i += 256) {
        reinterpret_cast<float4*>(Bs)[i] = reinterpret_cast<const float4*>(W)[i];
    }
    __syncthreads();

    int tm = tid >> 5;     // 0..7
    int tn = tid & 31;     // 0..31

    float acc[8][TN];
    #pragma unroll
    for (int i = 0; i < 8; i++)
        #pragma unroll
        for (int j = 0; j < TN; j++) acc[i][j] = 0.f;

    const float* arow = As + tm * 8 * AS_STRIDE;

    #pragma unroll 4
    for (int k = 0; k < K; ++k) {
        float bf[TN];
        if (TN == 4) {
            float4 b4 = reinterpret_cast<const float4*>(Bs + k * NOUT)[tn];
            bf[0] = b4.x; bf[1] = b4.y; bf[2] = b4.z; bf[3] = b4.w;
        } else {
            float2 b2 = reinterpret_cast<const float2*>(Bs + k * NOUT)[tn];
            bf[0] = b2.x; bf[1] = b2.y;
        }
        #pragma unroll
        for (int i = 0; i < 8; i++) {
            float a = arow[i * AS_STRIDE + k];
            #pragma unroll
            for (int j = 0; j < TN; j++) acc[i][j] += a * bf[j];
        }
    }

    // --- epilogue: bias (+ relu) + vectorized store ---
    float bb[TN];
    #pragma unroll
    for (int j = 0; j < TN; j++) bb[j] = bias[tn * TN + j];

    #pragma unroll
    for (int i = 0; i < 8; i++) {
        int node = m0 + tm * 8 + i;
        if (node >= N_NODES) break;
        float o[TN];
        #pragma unroll
        for (int j = 0; j < TN; j++) {
            float v = acc[i][j] + bb[j];
            if (RELU) v = fmaxf(v, 0.f);
            o[j] = v;
        }
        if (TN == 4) {
            float4 s = make_float4(o[0], o[1], o[2], o[3]);
            reinterpret_cast<float4*>(out + (size_t)node * NOUT)[tn] = s;
        } else {
            float2 s = make_float2(o[0], o[1]);
            reinterpret_cast<float2*>(out + (size_t)node * NOUT)[tn] = s;
        }
    }
}

// ---------------- launch ---------------------------------------------------
extern "C" void kernel_launch(void* const* d_in, const int* in_sizes, int n_in,
                              void* d_out, int out_size) {
    const float* x  = (const float*)d_in[0];
    const int*   ei = (const int*)  d_in[1];
    const float* W1 = (const float*)d_in[2];
    const float* b1 = (const float*)d_in[3];
    const float* W2 = (const float*)d_in[4];
    const float* b2 = (const float*)d_in[5];
    const float* W3 = (const float*)d_in[6];
    const float* b3 = (const float*)d_in[7];
    const float* W4 = (const float*)d_in[8];
    const float* b4 = (const float*)d_in[9];
    float* out = (float*)d_out;

    float *agg, *h1, *h2;
    cudaGetSymbolAddress((void**)&agg, g_agg4);
    cudaGetSymbolAddress((void**)&h1,  g_h1_4);
    cudaGetSymbolAddress((void**)&h2,  g_h2_4);

    const size_t smem128 = (size_t)(64 * 132 + 128 * 128) * sizeof(float); // 99328
    const size_t smem64  = (size_t)(64 * 132 + 128 * 64)  * sizeof(float); // 66560
    cudaFuncSetAttribute(mlp_kernel<128, true,  true >, cudaFuncAttributeMaxDynamicSharedMemorySize, (int)smem128);
    cudaFuncSetAttribute(mlp_kernel<128, true,  false>, cudaFuncAttributeMaxDynamicSharedMemorySize, (int)smem128);
    cudaFuncSetAttribute(mlp_kernel<64,  false, false>, cudaFuncAttributeMaxDynamicSharedMemorySize, (int)smem64);

    // 1) zero agg + deg
    {
        int n4 = (N_NODES * IN_DIM) / 4;
        int blocks = (n4 + 255) / 256;
        zero_kernel<<<blocks, 256>>>();
    }
    // 2) scatter-add (8 threads / edge)
    {
        long long threads = (long long)N_EDGES * 8;
        int blocks = (int)((threads + 255) / 256);
        scatter_kernel<<<blocks, 256>>>(x, ei);
    }
    // 3) agg /= max(deg, 1)
    {
        int n4 = N_NODES * (IN_DIM / 4);
        int blocks = (n4 + 255) / 256;
        finalize_kernel<<<blocks, 256>>>();
    }
    // 4) MLP
    int gblocks = (N_NODES + 63) / 64;  // 1563
    mlp_kernel<128, true,  true ><<<gblocks, 256, smem128>>>(x,  agg,     W1, b1, h1);
    mlp_kernel<128, true,  false><<<gblocks, 256, smem128>>>(h1, nullptr, W2, b2, h2);
    mlp_kernel<128, true,  false><<<gblocks, 256, smem128>>>(h2, nullptr, W3, b3, h1);
    mlp_kernel<64,  false, false><<<gblocks, 256, smem64 >>>(h1, nullptr, W4, b4, out);
}

// round 4
// speedup vs baseline: 1.1209x; 1.1209x over previous
#include <cuda_runtime.h>

#define N_NODES 100000
#define N_EDGES 1250000
#define IN_DIM  64
#define HID     128
#define OUT_DIM 64

// ---------------- scratch (static device globals; 16B-aligned) ------------
__device__ float4 g_agg4[(size_t)N_NODES * IN_DIM / 4];   // 25.6 MB
__device__ float  g_deg [N_NODES];
__device__ float4 g_h1_4[(size_t)N_NODES * HID / 4];      // 51.2 MB
__device__ float4 g_h2_4[(size_t)N_NODES * HID / 4];      // 51.2 MB

// ---------------- packed f32x2 helpers ------------------------------------
__device__ __forceinline__ unsigned long long pack2(float lo, float hi) {
    unsigned long long r;
    asm("mov.b64 %0, {%1, %2};" : "=l"(r) : "f"(lo), "f"(hi));
    return r;
}
__device__ __forceinline__ void ffma2(unsigned long long& d,
                                      unsigned long long a,
                                      unsigned long long b) {
    asm("fma.rn.f32x2 %0, %1, %2, %0;" : "+l"(d) : "l"(a), "l"(b));
}
__device__ __forceinline__ float2 unpack2(unsigned long long v) {
    float2 f;
    asm("mov.b64 {%0, %1}, %2;" : "=f"(f.x), "=f"(f.y) : "l"(v));
    return f;
}

__device__ __forceinline__ void red_add_v4(float* p, float4 v) {
    asm volatile("red.global.add.v4.f32 [%0], {%1, %2, %3, %4};"
                 :: "l"(p), "f"(v.x), "f"(v.y), "f"(v.z), "f"(v.w)
                 : "memory");
}

// ---------------- zero agg + deg ------------------------------------------
__global__ void zero_kernel() {
    int i = blockIdx.x * blockDim.x + threadIdx.x;
    const int n4 = (N_NODES * IN_DIM) / 4;
    if (i < n4) g_agg4[i] = make_float4(0.f, 0.f, 0.f, 0.f);
    if (i < N_NODES) g_deg[i] = 0.f;
}

// ---------------- scatter: agg[row] += x[col]; deg[row] += 1 --------------
__global__ void scatter_kernel(const float* __restrict__ x,
                               const int* __restrict__ ei) {
    long long t = (long long)blockIdx.x * blockDim.x + threadIdx.x;
    int e = (int)(t >> 3);
    if (e >= N_EDGES) return;
    int p = (int)(t & 7);
    int row = ei[e];
    int col = ei[N_EDGES + e];
    const float4* src = reinterpret_cast<const float4*>(x + (size_t)col * IN_DIM) + p * 2;
    float* dst = reinterpret_cast<float*>(g_agg4) + (size_t)row * IN_DIM + p * 8;
    float4 v0 = src[0];
    float4 v1 = src[1];
    red_add_v4(dst, v0);
    red_add_v4(dst + 4, v1);
    if (p == 0) atomicAdd(&g_deg[row], 1.0f);
}

// ---------------- finalize: agg /= max(deg,1) ------------------------------
__global__ void finalize_kernel() {
    int i = blockIdx.x * blockDim.x + threadIdx.x;
    const int n4 = N_NODES * (IN_DIM / 4);
    if (i >= n4) return;
    int node = i / (IN_DIM / 4);
    float inv = 1.0f / fmaxf(g_deg[node], 1.0f);
    float4 v = g_agg4[i];
    v.x *= inv; v.y *= inv; v.z *= inv; v.w *= inv;
    g_agg4[i] = v;
}

// ---------------- fused-layer SGEMM, packed f32x2 FFMA2 -------------------
// out[M, NOUT] = act(A[M,128] @ W[128,NOUT] + b)
// BM=64 rows/block, 256 threads. Thread: 8 rows x TN cols, rows packed in pairs.
// As stored k-major [K][BM]: per-k A fragment = 2 broadcast LDS.128.
template<int NOUT, bool RELU, bool CONCAT>
__global__ void mlp_kernel(const float* __restrict__ A,
                           const float* __restrict__ A2,
                           const float* __restrict__ W,
                           const float* __restrict__ bias,
                           float* __restrict__ out) {
    constexpr int K = 128;
    constexpr int BM = 64;
    constexpr int TN = NOUT / 32;

    extern __shared__ float smem[];
    float* As = smem;              // [K][BM]  (transposed)
    float* Bs = smem + K * BM;     // [K][NOUT]

    int tid = threadIdx.x;
    int m0 = blockIdx.x * BM;

    // --- fill As transposed: thread i -> (m = i&63, kq = i>>6), 4 k's ---
    for (int i = tid; i < BM * (K / 4); i += 256) {
        int m  = i & 63;
        int kq = i >> 6;            // 0..31, covers k = 4*kq..4*kq+3
        int node = m0 + m;
        float4 v = make_float4(0.f, 0.f, 0.f, 0.f);
        if (node < N_NODES) {
            if (CONCAT) {
                if (kq < 16) v = reinterpret_cast<const float4*>(A )[(size_t)node * 16 + kq];
                else         v = reinterpret_cast<const float4*>(A2)[(size_t)node * 16 + kq - 16];
            } else {
                v = reinterpret_cast<const float4*>(A)[(size_t)node * 32 + kq];
            }
        }
        int k0 = kq * 4;
        As[(k0 + 0) * BM + m] = v.x;
        As[(k0 + 1) * BM + m] = v.y;
        As[(k0 + 2) * BM + m] = v.z;
        As[(k0 + 3) * BM + m] = v.w;
    }
    // --- fill Bs [K][NOUT] ---
    for (int i = tid; i < K * NOUT / 4; i += 256) {
        reinterpret_cast<float4*>(Bs)[i] = reinterpret_cast<const float4*>(W)[i];
    }
    __syncthreads();

    int tm = tid >> 5;     // 0..7  (warp id -> 8-row slab)
    int tn = tid & 31;     // lane  -> TN-col group

    unsigned long long acc[4][TN];
    #pragma unroll
    for (int r = 0; r < 4; r++)
        #pragma unroll
        for (int j = 0; j < TN; j++) acc[r][j] = 0ull;

    const float* abase = As + tm * 8;

    #pragma unroll 4
    for (int k = 0; k < K; ++k) {
        const float* ar = abase + k * BM;
        float4 a0 = *reinterpret_cast<const float4*>(ar);
        float4 a1 = *reinterpret_cast<const float4*>(ar + 4);
        unsigned long long aa[4];
        aa[0] = pack2(a0.x, a0.y);
        aa[1] = pack2(a0.z, a0.w);
        aa[2] = pack2(a1.x, a1.y);
        aa[3] = pack2(a1.z, a1.w);

        unsigned long long bbp[TN];
        if (TN == 4) {
            float4 b4 = reinterpret_cast<const float4*>(Bs + k * NOUT)[tn];
            bbp[0] = pack2(b4.x, b4.x);
            bbp[1] = pack2(b4.y, b4.y);
            bbp[2] = pack2(b4.z, b4.z);
            bbp[3] = pack2(b4.w, b4.w);
        } else {
            float2 b2 = reinterpret_cast<const float2*>(Bs + k * NOUT)[tn];
            bbp[0] = pack2(b2.x, b2.x);
            bbp[1] = pack2(b2.y, b2.y);
        }

        #pragma unroll
        for (int r = 0; r < 4; r++)
            #pragma unroll
            for (int j = 0; j < TN; j++)
                ffma2(acc[r][j], aa[r], bbp[j]);
    }

    // --- epilogue: bias (+relu), vectorized store, row-pair unpack ---
    float bb[TN];
    #pragma unroll
    for (int j = 0; j < TN; j++) bb[j] = bias[tn * TN + j];

    #pragma unroll
    for (int r = 0; r < 4; r++) {
        int row0 = m0 + tm * 8 + 2 * r;
        float o0[TN], o1[TN];
        #pragma unroll
        for (int j = 0; j < TN; j++) {
            float2 v = unpack2(acc[r][j]);
            float u0 = v.x + bb[j];
            float u1 = v.y + bb[j];
            if (RELU) { u0 = fmaxf(u0, 0.f); u1 = fmaxf(u1, 0.f); }
            o0[j] = u0; o1[j] = u1;
        }
        if (row0 < N_NODES) {
            if (TN == 4)
                reinterpret_cast<float4*>(out + (size_t)row0 * NOUT)[tn] =
                    make_float4(o0[0], o0[1], o0[2], o0[3]);
            else
                reinterpret_cast<float2*>(out + (size_t)row0 * NOUT)[tn] =
                    make_float2(o0[0], o0[1]);
        }
        if (row0 + 1 < N_NODES) {
            if (TN == 4)
                reinterpret_cast<float4*>(out + (size_t)(row0 + 1) * NOUT)[tn] =
                    make_float4(o1[0], o1[1], o1[2], o1[3]);
            else
                reinterpret_cast<float2*>(out + (size_t)(row0 + 1) * NOUT)[tn] =
                    make_float2(o1[0], o1[1]);
        }
    }
}

// ---------------- launch ---------------------------------------------------
extern "C" void kernel_launch(void* const* d_in, const int* in_sizes, int n_in,
                              void* d_out, int out_size) {
    const float* x  = (const float*)d_in[0];
    const int*   ei = (const int*)  d_in[1];
    const float* W1 = (const float*)d_in[2];
    const float* b1 = (const float*)d_in[3];
    const float* W2 = (const float*)d_in[4];
    const float* b2 = (const float*)d_in[5];
    const float* W3 = (const float*)d_in[6];
    const float* b3 = (const float*)d_in[7];
    const float* W4 = (const float*)d_in[8];
    const float* b4 = (const float*)d_in[9];
    float* out = (float*)d_out;

    float *agg, *h1, *h2;
    cudaGetSymbolAddress((void**)&agg, g_agg4);
    cudaGetSymbolAddress((void**)&h1,  g_h1_4);
    cudaGetSymbolAddress((void**)&h2,  g_h2_4);

    const size_t smem128 = (size_t)(128 * 64 + 128 * 128) * sizeof(float); // 98304
    const size_t smem64  = (size_t)(128 * 64 + 128 * 64)  * sizeof(float); // 65536
    cudaFuncSetAttribute(mlp_kernel<128, true,  true >, cudaFuncAttributeMaxDynamicSharedMemorySize, (int)smem128);
    cudaFuncSetAttribute(mlp_kernel<128, true,  false>, cudaFuncAttributeMaxDynamicSharedMemorySize, (int)smem128);
    cudaFuncSetAttribute(mlp_kernel<64,  false, false>, cudaFuncAttributeMaxDynamicSharedMemorySize, (int)smem64);

    // 1) zero agg + deg
    {
        int n4 = (N_NODES * IN_DIM) / 4;
        zero_kernel<<<(n4 + 255) / 256, 256>>>();
    }
    // 2) scatter-add
    {
        long long threads = (long long)N_EDGES * 8;
        scatter_kernel<<<(int)((threads + 255) / 256), 256>>>(x, ei);
    }
    // 3) agg /= max(deg,1)
    {
        int n4 = N_NODES * (IN_DIM / 4);
        finalize_kernel<<<(n4 + 255) / 256, 256>>>();
    }
    // 4) MLP
    int gblocks = (N_NODES + 63) / 64;  // 1563
    mlp_kernel<128, true,  true ><<<gblocks, 256, smem128>>>(x,  agg,     W1, b1, h1);
    mlp_kernel<128, true,  false><<<gblocks, 256, smem128>>>(h1, nullptr, W2, b2, h2);
    mlp_kernel<128, true,  false><<<gblocks, 256, smem128>>>(h2, nullptr, W3, b3, h1);
    mlp_kernel<64,  false, false><<<gblocks, 256, smem64 >>>(h1, nullptr, W4, b4, out);
}